// round 14
// baseline (speedup 1.0000x reference)
#include <cuda_runtime.h>
#include <cuda_bf16.h>

// Problem dims
#define B_  32
#define S_  512
#define I_  256
#define H_  512
#define E_  1024
#define G_  2048
#define NH_ 16
#define HD_ 64
#define T_  16      // tail positions 496..511
#define S0_ 496

// ---------------- scratch (static device globals; no allocation) ----------------
__device__ float g_xg[(size_t)2 * S_ * G_ * B_];   // [dir][s][g][b]
__device__ float g_h [(size_t)2 * S_ * H_ * B_];   // [dir][s][j][b]
__device__ float g_hL[(size_t)B_ * T_ * E_];       // [b][t][e], t = s-496
__device__ float g_K [(size_t)B_ * T_ * E_];       // [m][hk*64+d], m=b*16+t
__device__ float g_V [(size_t)B_ * T_ * E_];
__device__ float g_Q15[(size_t)B_ * T_ * HD_];     // [m][d] head-15 query
__device__ float g_last[B_ * E_];                  // last[b][e]
__device__ float g_we[E_];                         // Wo^T @ Wfc^T
__device__ unsigned g_cnt[2];
__device__ unsigned g_gen[2];

// ---------------- accurate fp32 exp (explicit FMA; fast-math-proof) -------------
__device__ __forceinline__ float expf_acc(float x) {
    x = fminf(fmaxf(x, -87.0f), 87.0f);
    float n = rintf(x * 1.44269504088896341f);
    float r = fmaf(n, -0.693359375f, x);
    r = fmaf(n, 2.12194440e-4f, r);
    float p =             1.9875691500e-4f;
    p = fmaf(p, r, 1.3981999507e-3f);
    p = fmaf(p, r, 8.3334519073e-3f);
    p = fmaf(p, r, 4.1665795894e-2f);
    p = fmaf(p, r, 1.6666665459e-1f);
    p = fmaf(p, r, 5.0000001201e-1f);
    p = fmaf(p * r, r, r) + 1.0f;
    float sc = __int_as_float(((int)n + 127) << 23);
    return p * sc;
}
__device__ __forceinline__ float sigf(float x)   { return 1.0f / (1.0f + expf_acc(-x)); }
__device__ __forceinline__ float tanhf_(float x) { return 1.0f - 2.0f / (expf_acc(2.0f * x) + 1.0f); }

// ---------------- K0: reset barrier state (first node of every replay) ----------
__global__ void k_reset() {
    if (threadIdx.x < 2) { g_cnt[threadIdx.x] = 0u; g_gen[threadIdx.x] = 0u; }
}

// ---------------- w_eff[e] = sum_f Wfc[f] * Wo[f][e] ----------------------------
__global__ __launch_bounds__(128) void k_weff(const float* __restrict__ Wo,
                                              const float* __restrict__ Wfc) {
    int e = blockIdx.x * 128 + threadIdx.x;
    float acc = 0.f;
    for (int f = 0; f < E_; ++f) acc += Wfc[f] * Wo[(size_t)f * E_ + e];
    g_we[e] = acc;
}

// ---------------- xg[dir][s][g][b] = x[b,s,:] . W_ih[g,:] + bias[g] -------------
__global__ __launch_bounds__(256) void k_xg(
    const float* __restrict__ x,
    const float* __restrict__ W, const float* __restrict__ bias,
    int dir, int s_base)
{
    const int s  = s_base + blockIdx.y;
    const int g0 = blockIdx.x * 64;
    const int tid = threadIdx.x;

    __shared__ float Ws[64 * 36];
    __shared__ float xs[32 * 33];

    const int b  = tid & 31;
    const int gl = tid >> 5;

    float acc[8];
#pragma unroll
    for (int u = 0; u < 8; ++u) acc[u] = 0.f;

    for (int k0 = 0; k0 < I_; k0 += 32) {
        for (int i4 = tid; i4 < 512; i4 += 256) {
            int g = i4 >> 3, kk = (i4 & 7) * 4;
            float4 v = *(const float4*)&W[(size_t)(g0 + g) * I_ + k0 + kk];
            *(float4*)&Ws[g * 36 + kk] = v;
        }
        {
            int b2 = tid >> 3, kk0 = (tid & 7) * 4;
            float4 v = *(const float4*)&x[((size_t)b2 * S_ + s) * I_ + k0 + kk0];
            xs[(kk0 + 0) * 33 + b2] = v.x;
            xs[(kk0 + 1) * 33 + b2] = v.y;
            xs[(kk0 + 2) * 33 + b2] = v.z;
            xs[(kk0 + 3) * 33 + b2] = v.w;
        }
        __syncthreads();
#pragma unroll
        for (int kk4 = 0; kk4 < 8; ++kk4) {
            int k = kk4 * 4;
            float x0 = xs[(k + 0) * 33 + b];
            float x1 = xs[(k + 1) * 33 + b];
            float x2 = xs[(k + 2) * 33 + b];
            float x3 = xs[(k + 3) * 33 + b];
#pragma unroll
            for (int u = 0; u < 8; ++u) {
                float4 w = *(const float4*)&Ws[(gl * 8 + u) * 36 + k];
                acc[u] += w.x * x0 + w.y * x1 + w.z * x2 + w.w * x3;
            }
        }
        __syncthreads();
    }
    const size_t ob = ((size_t)dir * S_ + s) * (size_t)G_ * B_;
#pragma unroll
    for (int u = 0; u < 8; ++u) {
        int g = g0 + gl * 8 + u;
        g_xg[ob + (size_t)g * B_ + b] = acc[u] + bias[g];
    }
}

// ---------------- persistent LSTM scan (one direction, nsteps steps) ------------
// 64 CTAs, each owns 8 hidden units x 32 batches; W_hh slice in smem for the
// whole scan; per-step global barrier (counter set `bidx`).
__global__ __launch_bounds__(256, 1) void k_scan(
    const float* __restrict__ Whh, int nsteps, int bidx)
{
    extern __shared__ float smem[];
    float* W_sm = smem;               // [4][8][512]  64 KB
    float* h_sm = smem + 4 * 8 * 512; // [512][32]    64 KB

    const int dir = bidx;             // 0 fwd, 1 bwd
    const int cta = blockIdx.x;
    const int j0  = cta * 8;
    const int tid = threadIdx.x;
    const int b   = tid & 31;
    const int jl  = tid >> 5;
    const int jg  = j0 + jl;

    for (int i4 = tid; i4 < 4096; i4 += 256) {
        int flat = i4 * 4;
        int gate = flat >> 12;
        int rem  = flat & 4095;
        int jj   = rem >> 9;
        int k    = rem & 511;
        *(float4*)&W_sm[flat] =
            *(const float4*)&Whh[((size_t)(gate * 512 + j0 + jj)) * H_ + k];
    }
    __syncthreads();

    const float* Wi = &W_sm[(0 * 8 + jl) * 512];
    const float* Wf = &W_sm[(1 * 8 + jl) * 512];
    const float* Wg = &W_sm[(2 * 8 + jl) * 512];
    const float* Wo = &W_sm[(3 * 8 + jl) * 512];

    float c = 0.f;

    for (int si = 0; si < nsteps; ++si) {
        const int s = dir ? (S_ - 1 - si) : si;
        const size_t xb = ((size_t)dir * S_ + s) * (size_t)G_ * B_;
        float gi = g_xg[xb + (size_t)(0 * 512 + jg) * B_ + b];
        float gf = g_xg[xb + (size_t)(1 * 512 + jg) * B_ + b];
        float gg = g_xg[xb + (size_t)(2 * 512 + jg) * B_ + b];
        float go = g_xg[xb + (size_t)(3 * 512 + jg) * B_ + b];

        if (si > 0) {
            float ai[4] = {0.f, 0.f, 0.f, 0.f};
            float af[4] = {0.f, 0.f, 0.f, 0.f};
            float ag[4] = {0.f, 0.f, 0.f, 0.f};
            float ao[4] = {0.f, 0.f, 0.f, 0.f};
            const float* hp = h_sm + b;
#pragma unroll 4
            for (int k4 = 0; k4 < 128; ++k4) {
                int k = k4 * 4;
                float h0 = hp[(k + 0) * 32];
                float h1 = hp[(k + 1) * 32];
                float h2 = hp[(k + 2) * 32];
                float h3 = hp[(k + 3) * 32];
                float4 wi = *(const float4*)&Wi[k];
                float4 wf = *(const float4*)&Wf[k];
                float4 wg = *(const float4*)&Wg[k];
                float4 wo = *(const float4*)&Wo[k];
                ai[0] = fmaf(wi.x, h0, ai[0]); ai[1] = fmaf(wi.y, h1, ai[1]);
                ai[2] = fmaf(wi.z, h2, ai[2]); ai[3] = fmaf(wi.w, h3, ai[3]);
                af[0] = fmaf(wf.x, h0, af[0]); af[1] = fmaf(wf.y, h1, af[1]);
                af[2] = fmaf(wf.z, h2, af[2]); af[3] = fmaf(wf.w, h3, af[3]);
                ag[0] = fmaf(wg.x, h0, ag[0]); ag[1] = fmaf(wg.y, h1, ag[1]);
                ag[2] = fmaf(wg.z, h2, ag[2]); ag[3] = fmaf(wg.w, h3, ag[3]);
                ao[0] = fmaf(wo.x, h0, ao[0]); ao[1] = fmaf(wo.y, h1, ao[1]);
                ao[2] = fmaf(wo.z, h2, ao[2]); ao[3] = fmaf(wo.w, h3, ao[3]);
            }
            gi += (ai[0] + ai[1]) + (ai[2] + ai[3]);
            gf += (af[0] + af[1]) + (af[2] + af[3]);
            gg += (ag[0] + ag[1]) + (ag[2] + ag[3]);
            go += (ao[0] + ao[1]) + (ao[2] + ao[3]);
        }
        c = sigf(gf) * c + sigf(gi) * tanhf_(gg);
        float h = sigf(go) * tanhf_(c);

        const size_t hbase = ((size_t)dir * S_ + s) * (size_t)H_ * B_;
        g_h[hbase + (size_t)jg * B_ + b] = h;

        if (si < nsteps - 1) {
            __threadfence();
            __syncthreads();
            if (tid == 0) {
                unsigned arrived = atomicAdd(&g_cnt[bidx], 1u) + 1u;
                if (arrived == 64u) {
                    atomicExch(&g_cnt[bidx], 0u);
                    __threadfence();
                    atomicAdd(&g_gen[bidx], 1u);
                } else {
                    const unsigned target = (unsigned)(si + 1);
                    while (atomicAdd(&g_gen[bidx], 0u) < target) __nanosleep(64);
                }
            }
            __syncthreads();
            const float4* src = (const float4*)&g_h[hbase];
            float4* dst = (float4*)h_sm;
            for (int i = tid; i < 4096; i += 256) dst[i] = src[i];
            __syncthreads();
        }
    }
}

// ---------------- gather tail h into hL[b][t][e], e = dir*512 + j ---------------
__global__ __launch_bounds__(256) void k_gather() {
    __shared__ float t[32][33];
    const int dir = blockIdx.z;
    const int tt  = blockIdx.y;            // 0..15
    const int j0  = blockIdx.x * 32;
    const int tid = threadIdx.x;
    const int s   = S0_ + tt;
    const size_t base = ((size_t)dir * S_ + s) * (size_t)H_ * B_;
#pragma unroll
    for (int i = 0; i < 4; ++i) {
        int idx = tid + i * 256;
        int j = idx >> 5, b2 = idx & 31;
        t[j][b2] = g_h[base + (size_t)(j0 + j) * B_ + b2];
    }
    __syncthreads();
#pragma unroll
    for (int i = 0; i < 4; ++i) {
        int idx = tid + i * 256;
        int b2 = idx >> 5, j = idx & 31;
        g_hL[((size_t)b2 * T_ + tt) * E_ + dir * H_ + j0 + j] = t[j][b2];
    }
}

// ---------------- K/V projections at tail: out[m][n] = hL[m,:].W[n,:] + bias ----
// M = 512 (m=b*16+t), N = 1024, K = 1024. grid (16 n-tiles, 8 m-tiles, 2 {K,V}).
__global__ __launch_bounds__(256) void k_kv(
    const float* __restrict__ Wk, const float* __restrict__ bk,
    const float* __restrict__ Wv, const float* __restrict__ bv)
{
    const float* __restrict__ W    = blockIdx.z ? Wv : Wk;
    const float* __restrict__ bias = blockIdx.z ? bv : bk;
    float* __restrict__ out        = blockIdx.z ? g_V : g_K;

    const int n0 = blockIdx.x * 64;
    const int m0 = blockIdx.y * 64;
    const int tid = threadIdx.x;
    const int tx = tid & 15;    // n quad
    const int ty = tid >> 4;    // m quad

    __shared__ float As[32 * 68];   // [k][m]
    __shared__ float Bs[32 * 68];   // [k][n]

    float acc[4][4];
#pragma unroll
    for (int i = 0; i < 4; ++i)
#pragma unroll
        for (int j = 0; j < 4; ++j) acc[i][j] = 0.f;

    for (int k0 = 0; k0 < E_; k0 += 32) {
        for (int i4 = tid; i4 < 512; i4 += 256) {
            int m = i4 >> 3, k4 = (i4 & 7) * 4;
            float4 v = *(const float4*)&g_hL[(size_t)(m0 + m) * E_ + k0 + k4];
            As[(k4 + 0) * 68 + m] = v.x; As[(k4 + 1) * 68 + m] = v.y;
            As[(k4 + 2) * 68 + m] = v.z; As[(k4 + 3) * 68 + m] = v.w;
        }
        for (int i4 = tid; i4 < 512; i4 += 256) {
            int n = i4 >> 3, k4 = (i4 & 7) * 4;
            float4 v = *(const float4*)&W[(size_t)(n0 + n) * E_ + k0 + k4];
            Bs[(k4 + 0) * 68 + n] = v.x; Bs[(k4 + 1) * 68 + n] = v.y;
            Bs[(k4 + 2) * 68 + n] = v.z; Bs[(k4 + 3) * 68 + n] = v.w;
        }
        __syncthreads();
#pragma unroll 8
        for (int k = 0; k < 32; ++k) {
            float a0 = As[k * 68 + ty * 4 + 0];
            float a1 = As[k * 68 + ty * 4 + 1];
            float a2 = As[k * 68 + ty * 4 + 2];
            float a3 = As[k * 68 + ty * 4 + 3];
            float b0 = Bs[k * 68 + tx * 4 + 0];
            float b1 = Bs[k * 68 + tx * 4 + 1];
            float b2 = Bs[k * 68 + tx * 4 + 2];
            float b3 = Bs[k * 68 + tx * 4 + 3];
            acc[0][0] = fmaf(a0, b0, acc[0][0]); acc[0][1] = fmaf(a0, b1, acc[0][1]);
            acc[0][2] = fmaf(a0, b2, acc[0][2]); acc[0][3] = fmaf(a0, b3, acc[0][3]);
            acc[1][0] = fmaf(a1, b0, acc[1][0]); acc[1][1] = fmaf(a1, b1, acc[1][1]);
            acc[1][2] = fmaf(a1, b2, acc[1][2]); acc[1][3] = fmaf(a1, b3, acc[1][3]);
            acc[2][0] = fmaf(a2, b0, acc[2][0]); acc[2][1] = fmaf(a2, b1, acc[2][1]);
            acc[2][2] = fmaf(a2, b2, acc[2][2]); acc[2][3] = fmaf(a2, b3, acc[2][3]);
            acc[3][0] = fmaf(a3, b0, acc[3][0]); acc[3][1] = fmaf(a3, b1, acc[3][1]);
            acc[3][2] = fmaf(a3, b2, acc[3][2]); acc[3][3] = fmaf(a3, b3, acc[3][3]);
        }
        __syncthreads();
    }
#pragma unroll
    for (int i = 0; i < 4; ++i) {
        int m = m0 + ty * 4 + i;
#pragma unroll
        for (int j = 0; j < 4; ++j) {
            int n = n0 + tx * 4 + j;
            out[(size_t)m * E_ + n] = acc[i][j] + bias[n];
        }
    }
}

// ---------------- head-15 query at tail: Q15[m][d] ------------------------------
__global__ __launch_bounds__(256) void k_q15(const float* __restrict__ Wq,
                                             const float* __restrict__ bq) {
    const int m = blockIdx.x;               // 0..511
    const int tid = threadIdx.x;
    const int w = tid >> 5, lane = tid & 31;
    __shared__ float hs[E_];
    hs[tid] = g_hL[(size_t)m * E_ + tid];
    hs[tid + 256] = g_hL[(size_t)m * E_ + tid + 256];
    hs[tid + 512] = g_hL[(size_t)m * E_ + tid + 512];
    hs[tid + 768] = g_hL[(size_t)m * E_ + tid + 768];
    __syncthreads();
#pragma unroll
    for (int i = 0; i < 8; ++i) {
        int d = w * 8 + i;
        int f = 15 * HD_ + d;
        const float* wrow = &Wq[(size_t)f * E_];
        float acc = 0.f;
        for (int e = lane; e < E_; e += 32) acc = fmaf(hs[e], wrow[e], acc);
#pragma unroll
        for (int o = 16; o > 0; o >>= 1) acc += __shfl_down_sync(0xffffffffu, acc, o);
        if (lane == 0) g_Q15[m * HD_ + d] = acc + bq[f];
    }
}

// ---------------- per-position head attention + scatter into last ---------------
// scores[hk] = (1/8) sum_d Q15[m,d] K[m,hk*64+d]; softmax over 16 heads;
// last[b, t*64+d] = sum_hk a[hk] V[m, hk*64+d].
__global__ __launch_bounds__(128) void k_attn16() {
    const int m = blockIdx.x;               // b*16 + t
    const int tid = threadIdx.x;
    const int w = tid >> 5, lane = tid & 31;
    __shared__ float q[HD_];
    __shared__ float sc[NH_];
    __shared__ float a[NH_];
    if (tid < HD_) q[tid] = g_Q15[m * HD_ + tid];
    __syncthreads();
#pragma unroll
    for (int i = 0; i < 4; ++i) {
        int hk = w * 4 + i;
        const float* krow = &g_K[(size_t)m * E_ + hk * HD_];
        float acc = fmaf(q[lane], krow[lane], q[lane + 32] * krow[lane + 32]);
#pragma unroll
        for (int o = 16; o > 0; o >>= 1) acc += __shfl_down_sync(0xffffffffu, acc, o);
        if (lane == 0) sc[hk] = acc * 0.125f;
    }
    __syncthreads();
    if (tid == 0) {
        float mx = sc[0];
#pragma unroll
        for (int i = 1; i < NH_; ++i) mx = fmaxf(mx, sc[i]);
        float sum = 0.f;
#pragma unroll
        for (int i = 0; i < NH_; ++i) { float e = expf_acc(sc[i] - mx); a[i] = e; sum += e; }
        float inv = 1.f / sum;
#pragma unroll
        for (int i = 0; i < NH_; ++i) a[i] *= inv;
    }
    __syncthreads();
    if (tid < HD_) {
        const int d = tid;
        float acc = 0.f;
#pragma unroll
        for (int hk = 0; hk < NH_; ++hk)
            acc = fmaf(a[hk], g_V[(size_t)m * E_ + hk * HD_ + d], acc);
        const int b = m >> 4, t = m & 15;
        g_last[b * E_ + t * HD_ + d] = acc;
    }
}

// ---------------- out[b] = sigmoid(last . w_eff + bo.Wfc + bfc) -----------------
__global__ __launch_bounds__(256) void k_final(
    const float* __restrict__ bo, const float* __restrict__ Wfc,
    const float* __restrict__ bfc, float* __restrict__ out)
{
    const int b = blockIdx.x, tid = threadIdx.x;
    float acc = 0.f;
    for (int f = tid; f < E_; f += 256)
        acc += g_last[b * E_ + f] * g_we[f] + bo[f] * Wfc[f];
    __shared__ float red[8];
#pragma unroll
    for (int o = 16; o > 0; o >>= 1) acc += __shfl_xor_sync(0xffffffffu, acc, o);
    if ((tid & 31) == 0) red[tid >> 5] = acc;
    __syncthreads();
    if (tid == 0) {
        float t = 0.f;
#pragma unroll
        for (int i = 0; i < 8; ++i) t += red[i];
        t += bfc[0];
        out[b] = 1.f / (1.f + expf_acc(-t));
    }
}

// ---------------- launch ---------------------------------------------------------
extern "C" void kernel_launch(void* const* d_in, const int* in_sizes, int n_in,
                              void* d_out, int out_size) {
    (void)in_sizes; (void)n_in; (void)out_size;
    const float* x    = (const float*)d_in[0];
    const float* Wihf = (const float*)d_in[1];
    const float* Whhf = (const float*)d_in[2];
    const float* bf   = (const float*)d_in[3];
    const float* Wihb = (const float*)d_in[4];
    const float* Whhb = (const float*)d_in[5];
    const float* bb   = (const float*)d_in[6];
    const float* Wq   = (const float*)d_in[7];
    const float* bq   = (const float*)d_in[8];
    const float* Wk   = (const float*)d_in[9];
    const float* bk   = (const float*)d_in[10];
    const float* Wv   = (const float*)d_in[11];
    const float* bv   = (const float*)d_in[12];
    const float* Wo   = (const float*)d_in[13];
    const float* bo   = (const float*)d_in[14];
    const float* Wfc  = (const float*)d_in[15];
    const float* bfc  = (const float*)d_in[16];
    float* out = (float*)d_out;

    cudaFuncSetAttribute(k_scan, cudaFuncAttributeMaxDynamicSharedMemorySize, 131072);

    k_reset  <<<1, 32>>>();
    k_weff   <<<8, 128>>>(Wo, Wfc);
    k_xg     <<<dim3(32, 512, 1), 256>>>(x, Wihf, bf, 0, 0);     // fwd: all s
    k_xg     <<<dim3(32, 16, 1), 256>>>(x, Wihb, bb, 1, S0_);    // bwd: tail only
    k_scan   <<<64, 256, 131072>>>(Whhf, S_, 0);                 // fwd: full scan
    k_scan   <<<64, 256, 131072>>>(Whhb, T_, 1);                 // bwd: 16 steps
    k_gather <<<dim3(16, 16, 2), 256>>>();
    k_kv     <<<dim3(16, 8, 2), 256>>>(Wk, bk, Wv, bv);
    k_q15    <<<512, 256>>>(Wq, bq);
    k_attn16 <<<512, 128>>>();
    k_final  <<<32, 256>>>(bo, Wfc, bfc, out);
}